// round 11
// baseline (speedup 1.0000x reference)
#include <cuda_runtime.h>
#include <cstdint>

#define NB 8
#define NA 65536
#define NC 80
#define NM 32
#define IMG_WH 512.0f
#define TPB 256
#define F4R 20                     // float4 per classification row
#define BLOCKS_X (NA / TPB)        // 256 blocks/image
#define P2X 64                     // pass2 x-blocks per image
#define NEG_LN2_075 (-0.5198603854199589f)   // -0.75*ln(2)

// ---------------------------------------------------------------------------
// Scratch
// ---------------------------------------------------------------------------
__device__ float    g_part_cls[NB * BLOCKS_X];
__device__ float    g_part_reg[NB * BLOCKS_X];
__device__ int      g_part_np [NB * BLOCKS_X];
__device__ float    g_part_loc[NB * P2X];
__device__ unsigned g_used[NB];            // atomicOr from pass1; reset in finalize
__device__ int      g_poscnt[NB];          // reset in finalize
__device__ float4   g_pos_an[NB * NA];     // self-contained pos records
__device__ float4   g_pos_rp[NB * NA];
__device__ float    g_pos_lp[NB * NA];
__device__ int      g_ticket = 0;

__device__ __forceinline__ float warp_sum_f(float v) {
#pragma unroll
    for (int o = 16; o > 0; o >>= 1) v += __shfl_down_sync(0xffffffffu, v, o);
    return v;
}
__device__ __forceinline__ int warp_sum_i(int v) {
#pragma unroll
    for (int o = 16; o > 0; o >>= 1) v += __shfl_down_sync(0xffffffffu, v, o);
    return v;
}

// ---------------------------------------------------------------------------
// Kernel 1 (fused): flags, focal cls stream (+label fix), reg loss, pos records.
// ---------------------------------------------------------------------------
__global__ __launch_bounds__(TPB, 6)
void pass1_kernel(const float* __restrict__ cls,
                  const float* __restrict__ reg,
                  const float* __restrict__ loc,
                  const float* __restrict__ anc,
                  const float* __restrict__ ann) {
    const int b = blockIdx.y;
    const int i = blockIdx.x * TPB + threadIdx.x;   // global anchor

    __shared__ float4   sbox[NM];
    __shared__ float    slbl[NM];
    __shared__ float    sarea_eff[NM];     // 1e30 for invalid boxes
    __shared__ float    sw0[TPB];          // per-anchor weight: -0.75*ln2 or 0
    __shared__ unsigned s_used;
    __shared__ float    sc[TPB / 32], sr[TPB / 32];
    __shared__ int      sn[TPB / 32];

    if (threadIdx.x < NM) {
        const float* a5 = ann + ((size_t)b * NM + threadIdx.x) * 5;
        float4 bx = make_float4(a5[0], a5[1], a5[2], a5[3]);
        float lbl = a5[4];
        sbox[threadIdx.x] = bx;
        slbl[threadIdx.x] = lbl;
        sarea_eff[threadIdx.x] = (lbl == -1.0f) ? 1e30f
                               : (bx.z - bx.x) * (bx.w - bx.y);
    }
    if (threadIdx.x == 0) s_used = 0u;
    __syncthreads();

    const float4 an = __ldg(((const float4*)anc) + i);
    const float aw = an.z - an.x;
    const float ah = an.w - an.y;
    const float area_a = aw * ah;

    // ---- Phase A: pos/neg, division-free ----
    float maxPos = -1e30f;
    float maxNeg = -1e30f;
#pragma unroll 8
    for (int m = 0; m < NM; m++) {
        float4 bx = sbox[m];
        float iw = fmaxf(fminf(an.z, bx.z) - fmaxf(an.x, bx.x), 0.f);
        float ih = fmaxf(fminf(an.w, bx.w) - fmaxf(an.y, bx.y), 0.f);
        float inter = iw * ih;
        float sab = area_a + sarea_eff[m];
        maxPos = fmaxf(maxPos, fmaf(3.0f, inter, -sab));
        maxNeg = fmaxf(maxNeg, fmaf(3.5f, inter, -sab));
    }
    const bool pos = maxPos >= 0.f;
    const bool neg = maxNeg < 0.f;

    float reg_acc = 0.f;
    float cls_fix = 0.f;

    if (pos) {
        // ---- Phase B: first-max argmax (rare), division-free ----
        float bi = -1.f, bd = 1.f;
        int arg = 0;
#pragma unroll 1
        for (int m = 0; m < NM; m++) {
            float4 bx = sbox[m];
            float iw = fmaxf(fminf(an.z, bx.z) - fmaxf(an.x, bx.x), 0.f);
            float ih = fmaxf(fminf(an.w, bx.w) - fmaxf(an.y, bx.y), 0.f);
            float inter = iw * ih;
            float area_b = (bx.z - bx.x) * (bx.w - bx.y);
            float den = area_a + area_b - inter;
            bool invalid = (slbl[m] == -1.0f);
            float im = invalid ? -1.f : inter;
            float dm = invalid ?  1.f : den;
            if (im * bd > bi * dm) { bi = im; bd = dm; arg = m; }
        }
        const int lbl = (int)slbl[arg];

        // cls label-class fix (exact clamped formula)
        {
            float p = __ldg(cls + ((size_t)b * NA + i) * NC + lbl);
            p = fminf(fmaxf(p, 1e-4f), 1.f - 1e-4f);
            float q = 1.f - p;
            cls_fix = 0.25f * q * q * (-__logf(p)) - 0.75f * p * p * (-__logf(q));
        }

        // self-contained pos record
        float4 rp = __ldg(((const float4*)reg) + (size_t)b * NA + i);
        {
            int slot = atomicAdd(&g_poscnt[b], 1);
            size_t s = (size_t)b * NA + slot;
            g_pos_an[s] = an;
            g_pos_rp[s] = rp;
            g_pos_lp[s] = __ldg(loc + (size_t)b * NA + i);
        }

        // reg loss
        float4 bx = sbox[arg];
        float gwr = bx.z - bx.x;
        float ghr = bx.w - bx.y;
        float gcx = bx.x + 0.5f * gwr;
        float gcy = bx.y + 0.5f * ghr;
        float gw = fmaxf(gwr, 1.f);
        float gh = fmaxf(ghr, 1.f);
        float acx = an.x + 0.5f * aw;
        float acy = an.y + 0.5f * ah;
        float t0 = __fdividef(gcx - acx, aw) * 10.f;
        float t1 = __fdividef(gcy - acy, ah) * 10.f;
        float t2 = __logf(__fdividef(gw, aw)) * 5.f;
        float t3 = __logf(__fdividef(gh, ah)) * 5.f;
        float d0 = fabsf(t0 - rp.x);
        float d1 = fabsf(t1 - rp.y);
        float d2 = fabsf(t2 - rp.z);
        float d3 = fabsf(t3 - rp.w);
        const float th = 1.0f / 9.0f;
        reg_acc += (d0 <= th) ? 4.5f * d0 * d0 : d0 - 0.5f / 9.0f;
        reg_acc += (d1 <= th) ? 4.5f * d1 * d1 : d1 - 0.5f / 9.0f;
        reg_acc += (d2 <= th) ? 4.5f * d2 * d2 : d2 - 0.5f / 9.0f;
        reg_acc += (d3 <= th) ? 4.5f * d3 * d3 : d3 - 0.5f / 9.0f;
        atomicOr(&s_used, 1u << arg);
    }

    sw0[threadIdx.x] = (!pos && !neg) ? 0.f : NEG_LN2_075;
    __syncthreads();

    if (threadIdx.x == 0 && s_used) atomicOr(&g_used[b], s_used);

    // ---- Phase C: coalesced branch-free focal stream (4 ops/elt) ----
    const float4* rowbase =
        (const float4*)(cls + ((size_t)b * NA + (size_t)blockIdx.x * TPB) * NC);

    float cls_acc = 0.f;   // weighted log2 units (weight includes -0.75*ln2)
#pragma unroll 5
    for (int it = 0; it < F4R; it++) {
        int f4i = it * TPB + threadIdx.x;
        int la  = f4i / F4R;
        float w0 = sw0[la];
        float4 v = __ldcs(rowbase + f4i);
        float s4;
        s4 = v.x * v.x * __log2f(1.f - v.x);
        s4 = fmaf(v.y * v.y, __log2f(1.f - v.y), s4);
        s4 = fmaf(v.z * v.z, __log2f(1.f - v.z), s4);
        s4 = fmaf(v.w * v.w, __log2f(1.f - v.w), s4);
        cls_acc = fmaf(w0, s4, cls_acc);
    }
    cls_acc += cls_fix;

    // ---- block reduction ----
    float wc = warp_sum_f(cls_acc);
    float wr = warp_sum_f(reg_acc);
    int   wn = warp_sum_i(pos ? 1 : 0);
    int w = threadIdx.x >> 5, lane = threadIdx.x & 31;
    if (lane == 0) { sc[w] = wc; sr[w] = wr; sn[w] = wn; }
    __syncthreads();
    if (threadIdx.x == 0) {
        float tc = 0.f, tr = 0.f; int tn = 0;
#pragma unroll
        for (int k = 0; k < TPB / 32; k++) { tc += sc[k]; tr += sr[k]; tn += sn[k]; }
        int pidx = b * BLOCKS_X + blockIdx.x;
        g_part_cls[pidx] = tc;
        g_part_reg[pidx] = tr;
        g_part_np [pidx] = tn;
    }
}

// ---------------------------------------------------------------------------
// Kernel 2: loc loss over pos records (pipelined rcp-max) + ticket finalize.
// ---------------------------------------------------------------------------
__global__ __launch_bounds__(TPB)
void pass2_kernel(const float* __restrict__ ann, float* __restrict__ out) {
    const int b = blockIdx.y;
    const int n = g_poscnt[b];

    __shared__ float4 sbox[NM];
    __shared__ float  sae[NM];      // area for used boxes, 1e30 otherwise
    __shared__ float  sl[TPB / 32];

    if (threadIdx.x < 32) {
        bool valid = false;
        float4 bx = make_float4(0.f, 0.f, 0.f, 0.f);
        if (threadIdx.x < NM) {
            const float* a5 = ann + ((size_t)b * NM + threadIdx.x) * 5;
            bx = make_float4(a5[0], a5[1], a5[2], a5[3]);
            sbox[threadIdx.x] = bx;
            valid = (a5[4] != -1.0f);
        }
        unsigned vm = __ballot_sync(0xffffffffu, valid);
        unsigned mask = vm & g_used[b];
        if (threadIdx.x < NM)
            sae[threadIdx.x] = ((mask >> threadIdx.x) & 1u)
                             ? (bx.z - bx.x) * (bx.w - bx.y) : 1e30f;
    }
    __syncthreads();

    float loc_acc = 0.f;
    for (int j = blockIdx.x * TPB + threadIdx.x; j < n; j += P2X * TPB) {
        size_t s = (size_t)b * NA + j;
        float4 an = g_pos_an[s];
        float4 rp = g_pos_rp[s];
        float  lp = g_pos_lp[s];
        float aw = an.z - an.x;
        float ah = an.w - an.y;
        float acx = an.x + 0.5f * aw;
        float acy = an.y + 0.5f * ah;
        float pcx = acx + rp.x * 0.1f * aw, pcy = acy + rp.y * 0.1f * ah;
        float pw = __expf(rp.z * 0.2f) * aw, ph = __expf(rp.w * 0.2f) * ah;
        float sx1 = fminf(fmaxf(pcx - 0.5f * pw, 0.f), IMG_WH);
        float sy1 = fminf(fmaxf(pcy - 0.5f * ph, 0.f), IMG_WH);
        float sx2 = fminf(fmaxf(pcx + 0.5f * pw, 0.f), IMG_WH);
        float sy2 = fminf(fmaxf(pcy + 0.5f * ph, 0.f), IMG_WH);
        float area_s = (sx2 - sx1) * (sy2 - sy1);

        // pipelined max: unused boxes have sae=1e30 -> iou ~ 1e-25 ~ 0
        float best = 0.f;
#pragma unroll
        for (int m = 0; m < NM; m++) {
            float4 bx = sbox[m];
            float iw = fmaxf(fminf(sx2, bx.z) - fmaxf(sx1, bx.x), 0.f);
            float ih = fmaxf(fminf(sy2, bx.w) - fmaxf(sy1, bx.y), 0.f);
            float inter = iw * ih;
            float den = area_s + sae[m] - inter;   // >= 64 for used boxes
            best = fmaxf(best, __fdividef(inter, den));
        }
        float ls = fminf(fmaxf(1.f - fabsf(lp - best), 1e-4f), 1.f - 1e-4f);
        loc_acc += -__logf(ls);
    }

    float wl = warp_sum_f(loc_acc);
    int w = threadIdx.x >> 5, lane = threadIdx.x & 31;
    if (lane == 0) sl[w] = wl;
    __syncthreads();
    if (threadIdx.x == 0) {
        float tl = 0.f;
#pragma unroll
        for (int k = 0; k < TPB / 32; k++) tl += sl[k];
        g_part_loc[b * P2X + blockIdx.x] = tl;
        __threadfence();
    }
    __syncthreads();

    __shared__ int s_last;
    if (threadIdx.x == 0) {
        int t = atomicAdd(&g_ticket, 1);
        s_last = (t == (int)(gridDim.x * gridDim.y) - 1);
    }
    __syncthreads();
    if (!s_last) return;

    // ---- finalize ----
    __shared__ float f_c[NB], f_r[NB], f_l[NB];
    {
        int wi = threadIdx.x >> 5;
        int ln = threadIdx.x & 31;
        if (wi < NB) {
            float cs = 0.f, rs = 0.f, lsum = 0.f; int np = 0;
#pragma unroll
            for (int k = 0; k < BLOCKS_X / 32; k++) {
                int p = wi * BLOCKS_X + k * 32 + ln;
                cs += g_part_cls[p];
                rs += g_part_reg[p];
                np += g_part_np[p];
            }
#pragma unroll
            for (int k = 0; k < P2X / 32; k++)
                lsum += g_part_loc[wi * P2X + k * 32 + ln];
            cs = warp_sum_f(cs); rs = warp_sum_f(rs);
            lsum = warp_sum_f(lsum); np = warp_sum_i(np);
            bool v = (ln < NM) && (ann[((size_t)wi * NM + ln) * 5 + 4] != -1.0f);
            bool has_gt = __ballot_sync(0xffffffffu, v) != 0u;
            if (ln == 0) {
                float fnp = (float)np;
                bool ok = has_gt && (np > 0);
                f_c[wi] = has_gt ? cs / fmaxf(fnp, 1.f)       : 0.f;
                f_r[wi] = ok     ? rs / fmaxf(fnp * 4.f, 1.f) : 0.f;
                f_l[wi] = ok     ? lsum / fmaxf(fnp, 1.f)     : 0.f;
            }
        }
    }
    __syncthreads();
    if (threadIdx.x == 0) {
        float c = 0.f, r = 0.f, l = 0.f;
#pragma unroll
        for (int k = 0; k < NB; k++) { c += f_c[k]; r += f_r[k]; l += f_l[k]; }
        out[0] = c / (float)NB;
        out[1] = r / (float)NB;
        out[2] = l / (float)NB;
        g_ticket = 0;
#pragma unroll
        for (int k = 0; k < NB; k++) { g_poscnt[k] = 0; g_used[k] = 0u; }
    }
}

// ---------------------------------------------------------------------------
extern "C" void kernel_launch(void* const* d_in, const int* in_sizes, int n_in,
                              void* d_out, int out_size) {
    const float* cls = (const float*)d_in[0];
    const float* reg = (const float*)d_in[1];
    const float* loc = (const float*)d_in[2];
    const float* anc = (const float*)d_in[3];
    const float* ann = (const float*)d_in[4];
    float* out = (float*)d_out;

    pass1_kernel<<<dim3(BLOCKS_X, NB), TPB>>>(cls, reg, loc, anc, ann);
    pass2_kernel<<<dim3(P2X, NB), TPB>>>(ann, out);
}

// round 12
// speedup vs baseline: 1.0436x; 1.0436x over previous
#include <cuda_runtime.h>
#include <cstdint>

#define NB 8
#define NA 65536
#define NC 80
#define NM 32
#define IMG_WH 512.0f
#define TPB 256
#define F4R 20                     // float4 per classification row
#define BLOCKS_X (NA / TPB)        // 256 blocks/image
#define P2X 64                     // pass2 x-blocks per image
#define NEG_LN2_075 (-0.5198603854199589f)   // -0.75*ln(2)

// ---------------------------------------------------------------------------
// Scratch
// ---------------------------------------------------------------------------
__device__ float    g_part_cls[NB * BLOCKS_X];
__device__ float    g_part_reg[NB * BLOCKS_X];
__device__ int      g_part_np [NB * BLOCKS_X];
__device__ float    g_part_loc[NB * P2X];
__device__ unsigned g_used[NB];            // atomicOr from pass1; reset in finalize
__device__ int      g_poscnt[NB];          // reset in finalize
__device__ float4   g_pos_an[NB * NA];     // self-contained pos records
__device__ float4   g_pos_rp[NB * NA];
__device__ float    g_pos_lp[NB * NA];
__device__ int      g_ticket = 0;

__device__ __forceinline__ float warp_sum_f(float v) {
#pragma unroll
    for (int o = 16; o > 0; o >>= 1) v += __shfl_down_sync(0xffffffffu, v, o);
    return v;
}
__device__ __forceinline__ int warp_sum_i(int v) {
#pragma unroll
    for (int o = 16; o > 0; o >>= 1) v += __shfl_down_sync(0xffffffffu, v, o);
    return v;
}

// ---------------------------------------------------------------------------
// Kernel 1 (fused): flags, focal cls stream (+label fix), reg loss, pos records.
// ---------------------------------------------------------------------------
__global__ __launch_bounds__(TPB, 6)
void pass1_kernel(const float* __restrict__ cls,
                  const float* __restrict__ reg,
                  const float* __restrict__ loc,
                  const float* __restrict__ anc,
                  const float* __restrict__ ann) {
    const int b = blockIdx.y;
    const int i = blockIdx.x * TPB + threadIdx.x;   // global anchor

    __shared__ float4   sbox[NM];
    __shared__ float    slbl[NM];
    __shared__ float    sarea_eff[NM];     // 1e30 for invalid boxes
    __shared__ float    sw0[TPB];          // per-anchor weight: -0.75*ln2 or 0
    __shared__ unsigned s_used;
    __shared__ float    sc[TPB / 32], sr[TPB / 32];
    __shared__ int      sn[TPB / 32];

    if (threadIdx.x < NM) {
        const float* a5 = ann + ((size_t)b * NM + threadIdx.x) * 5;
        float4 bx = make_float4(a5[0], a5[1], a5[2], a5[3]);
        float lbl = a5[4];
        sbox[threadIdx.x] = bx;
        slbl[threadIdx.x] = lbl;
        sarea_eff[threadIdx.x] = (lbl == -1.0f) ? 1e30f
                               : (bx.z - bx.x) * (bx.w - bx.y);
    }
    if (threadIdx.x == 0) s_used = 0u;
    __syncthreads();

    const float4 an = __ldg(((const float4*)anc) + i);
    const float aw = an.z - an.x;
    const float ah = an.w - an.y;
    const float area_a = aw * ah;

    // ---- Phase A: pos/neg, division-free ----
    float maxPos = -1e30f;
    float maxNeg = -1e30f;
#pragma unroll 8
    for (int m = 0; m < NM; m++) {
        float4 bx = sbox[m];
        float iw = fmaxf(fminf(an.z, bx.z) - fmaxf(an.x, bx.x), 0.f);
        float ih = fmaxf(fminf(an.w, bx.w) - fmaxf(an.y, bx.y), 0.f);
        float inter = iw * ih;
        float sab = area_a + sarea_eff[m];
        maxPos = fmaxf(maxPos, fmaf(3.0f, inter, -sab));
        maxNeg = fmaxf(maxNeg, fmaf(3.5f, inter, -sab));
    }
    const bool pos = maxPos >= 0.f;
    const bool neg = maxNeg < 0.f;

    float reg_acc = 0.f;
    float cls_fix = 0.f;

    if (pos) {
        // ---- Phase B: first-max argmax (rare), division-free ----
        float bi = -1.f, bd = 1.f;
        int arg = 0;
#pragma unroll 1
        for (int m = 0; m < NM; m++) {
            float4 bx = sbox[m];
            float iw = fmaxf(fminf(an.z, bx.z) - fmaxf(an.x, bx.x), 0.f);
            float ih = fmaxf(fminf(an.w, bx.w) - fmaxf(an.y, bx.y), 0.f);
            float inter = iw * ih;
            float area_b = (bx.z - bx.x) * (bx.w - bx.y);
            float den = area_a + area_b - inter;
            bool invalid = (slbl[m] == -1.0f);
            float im = invalid ? -1.f : inter;
            float dm = invalid ?  1.f : den;
            if (im * bd > bi * dm) { bi = im; bd = dm; arg = m; }
        }
        const int lbl = (int)slbl[arg];

        // cls label-class fix (exact clamped formula)
        {
            float p = __ldg(cls + ((size_t)b * NA + i) * NC + lbl);
            p = fminf(fmaxf(p, 1e-4f), 1.f - 1e-4f);
            float q = 1.f - p;
            cls_fix = 0.25f * q * q * (-__logf(p)) - 0.75f * p * p * (-__logf(q));
        }

        // self-contained pos record
        float4 rp = __ldg(((const float4*)reg) + (size_t)b * NA + i);
        {
            int slot = atomicAdd(&g_poscnt[b], 1);
            size_t s = (size_t)b * NA + slot;
            g_pos_an[s] = an;
            g_pos_rp[s] = rp;
            g_pos_lp[s] = __ldg(loc + (size_t)b * NA + i);
        }

        // reg loss
        float4 bx = sbox[arg];
        float gwr = bx.z - bx.x;
        float ghr = bx.w - bx.y;
        float gcx = bx.x + 0.5f * gwr;
        float gcy = bx.y + 0.5f * ghr;
        float gw = fmaxf(gwr, 1.f);
        float gh = fmaxf(ghr, 1.f);
        float acx = an.x + 0.5f * aw;
        float acy = an.y + 0.5f * ah;
        float t0 = __fdividef(gcx - acx, aw) * 10.f;
        float t1 = __fdividef(gcy - acy, ah) * 10.f;
        float t2 = __logf(__fdividef(gw, aw)) * 5.f;
        float t3 = __logf(__fdividef(gh, ah)) * 5.f;
        float d0 = fabsf(t0 - rp.x);
        float d1 = fabsf(t1 - rp.y);
        float d2 = fabsf(t2 - rp.z);
        float d3 = fabsf(t3 - rp.w);
        const float th = 1.0f / 9.0f;
        reg_acc += (d0 <= th) ? 4.5f * d0 * d0 : d0 - 0.5f / 9.0f;
        reg_acc += (d1 <= th) ? 4.5f * d1 * d1 : d1 - 0.5f / 9.0f;
        reg_acc += (d2 <= th) ? 4.5f * d2 * d2 : d2 - 0.5f / 9.0f;
        reg_acc += (d3 <= th) ? 4.5f * d3 * d3 : d3 - 0.5f / 9.0f;
        atomicOr(&s_used, 1u << arg);
    }

    sw0[threadIdx.x] = (!pos && !neg) ? 0.f : NEG_LN2_075;
    __syncthreads();

    if (threadIdx.x == 0 && s_used) atomicOr(&g_used[b], s_used);

    // ---- Phase C: coalesced branch-free focal stream (4 ops/elt) ----
    const float4* rowbase =
        (const float4*)(cls + ((size_t)b * NA + (size_t)blockIdx.x * TPB) * NC);

    float cls_acc = 0.f;   // weighted log2 units (weight includes -0.75*ln2)
#pragma unroll 5
    for (int it = 0; it < F4R; it++) {
        int f4i = it * TPB + threadIdx.x;
        int la  = f4i / F4R;
        float w0 = sw0[la];
        float4 v = __ldcs(rowbase + f4i);
        float s4;
        s4 = v.x * v.x * __log2f(1.f - v.x);
        s4 = fmaf(v.y * v.y, __log2f(1.f - v.y), s4);
        s4 = fmaf(v.z * v.z, __log2f(1.f - v.z), s4);
        s4 = fmaf(v.w * v.w, __log2f(1.f - v.w), s4);
        cls_acc = fmaf(w0, s4, cls_acc);
    }
    cls_acc += cls_fix;

    // ---- block reduction ----
    float wc = warp_sum_f(cls_acc);
    float wr = warp_sum_f(reg_acc);
    int   wn = warp_sum_i(pos ? 1 : 0);
    int w = threadIdx.x >> 5, lane = threadIdx.x & 31;
    if (lane == 0) { sc[w] = wc; sr[w] = wr; sn[w] = wn; }
    __syncthreads();
    if (threadIdx.x == 0) {
        float tc = 0.f, tr = 0.f; int tn = 0;
#pragma unroll
        for (int k = 0; k < TPB / 32; k++) { tc += sc[k]; tr += sr[k]; tn += sn[k]; }
        int pidx = b * BLOCKS_X + blockIdx.x;
        g_part_cls[pidx] = tc;
        g_part_reg[pidx] = tr;
        g_part_np [pidx] = tn;
    }
}

// ---------------------------------------------------------------------------
// Kernel 2: loc loss over pos records (rcp-max, bounded unroll) + finalize.
// ---------------------------------------------------------------------------
__global__ __launch_bounds__(TPB, 8)
void pass2_kernel(const float* __restrict__ ann, float* __restrict__ out) {
    const int b = blockIdx.y;
    const int n = g_poscnt[b];

    __shared__ float4 sbox[NM];
    __shared__ float  sae[NM];      // area for used boxes, 1e30 otherwise
    __shared__ float  sl[TPB / 32];

    if (threadIdx.x < 32) {
        bool valid = false;
        float4 bx = make_float4(0.f, 0.f, 0.f, 0.f);
        if (threadIdx.x < NM) {
            const float* a5 = ann + ((size_t)b * NM + threadIdx.x) * 5;
            bx = make_float4(a5[0], a5[1], a5[2], a5[3]);
            sbox[threadIdx.x] = bx;
            valid = (a5[4] != -1.0f);
        }
        unsigned vm = __ballot_sync(0xffffffffu, valid);
        unsigned mask = vm & g_used[b];
        if (threadIdx.x < NM)
            sae[threadIdx.x] = ((mask >> threadIdx.x) & 1u)
                             ? (bx.z - bx.x) * (bx.w - bx.y) : 1e30f;
    }
    __syncthreads();

    float loc_acc = 0.f;
    for (int j = blockIdx.x * TPB + threadIdx.x; j < n; j += P2X * TPB) {
        size_t s = (size_t)b * NA + j;
        float4 an = g_pos_an[s];
        float4 rp = g_pos_rp[s];
        float  lp = g_pos_lp[s];
        float aw = an.z - an.x;
        float ah = an.w - an.y;
        float acx = an.x + 0.5f * aw;
        float acy = an.y + 0.5f * ah;
        float pcx = acx + rp.x * 0.1f * aw, pcy = acy + rp.y * 0.1f * ah;
        float pw = __expf(rp.z * 0.2f) * aw, ph = __expf(rp.w * 0.2f) * ah;
        float sx1 = fminf(fmaxf(pcx - 0.5f * pw, 0.f), IMG_WH);
        float sy1 = fminf(fmaxf(pcy - 0.5f * ph, 0.f), IMG_WH);
        float sx2 = fminf(fmaxf(pcx + 0.5f * pw, 0.f), IMG_WH);
        float sy2 = fminf(fmaxf(pcy + 0.5f * ph, 0.f), IMG_WH);
        float area_s = (sx2 - sx1) * (sy2 - sy1);

        // pipelined max, unroll bounded to keep regs low:
        // unused boxes have sae=1e30 -> iou ~ 1e-25 ~ 0
        float best = 0.f;
#pragma unroll 4
        for (int m = 0; m < NM; m++) {
            float4 bx = sbox[m];
            float iw = fmaxf(fminf(sx2, bx.z) - fmaxf(sx1, bx.x), 0.f);
            float ih = fmaxf(fminf(sy2, bx.w) - fmaxf(sy1, bx.y), 0.f);
            float inter = iw * ih;
            float den = area_s + sae[m] - inter;   // >= 64 for used boxes
            best = fmaxf(best, __fdividef(inter, den));
        }
        float ls = fminf(fmaxf(1.f - fabsf(lp - best), 1e-4f), 1.f - 1e-4f);
        loc_acc += -__logf(ls);
    }

    float wl = warp_sum_f(loc_acc);
    int w = threadIdx.x >> 5, lane = threadIdx.x & 31;
    if (lane == 0) sl[w] = wl;
    __syncthreads();
    if (threadIdx.x == 0) {
        float tl = 0.f;
#pragma unroll
        for (int k = 0; k < TPB / 32; k++) tl += sl[k];
        g_part_loc[b * P2X + blockIdx.x] = tl;
        __threadfence();
    }
    __syncthreads();

    __shared__ int s_last;
    if (threadIdx.x == 0) {
        int t = atomicAdd(&g_ticket, 1);
        s_last = (t == (int)(gridDim.x * gridDim.y) - 1);
    }
    __syncthreads();
    if (!s_last) return;

    // ---- finalize ----
    __shared__ float f_c[NB], f_r[NB], f_l[NB];
    {
        int wi = threadIdx.x >> 5;
        int ln = threadIdx.x & 31;
        if (wi < NB) {
            float cs = 0.f, rs = 0.f, lsum = 0.f; int np = 0;
#pragma unroll
            for (int k = 0; k < BLOCKS_X / 32; k++) {
                int p = wi * BLOCKS_X + k * 32 + ln;
                cs += g_part_cls[p];
                rs += g_part_reg[p];
                np += g_part_np[p];
            }
#pragma unroll
            for (int k = 0; k < P2X / 32; k++)
                lsum += g_part_loc[wi * P2X + k * 32 + ln];
            cs = warp_sum_f(cs); rs = warp_sum_f(rs);
            lsum = warp_sum_f(lsum); np = warp_sum_i(np);
            bool v = (ln < NM) && (ann[((size_t)wi * NM + ln) * 5 + 4] != -1.0f);
            bool has_gt = __ballot_sync(0xffffffffu, v) != 0u;
            if (ln == 0) {
                float fnp = (float)np;
                bool ok = has_gt && (np > 0);
                f_c[wi] = has_gt ? cs / fmaxf(fnp, 1.f)       : 0.f;
                f_r[wi] = ok     ? rs / fmaxf(fnp * 4.f, 1.f) : 0.f;
                f_l[wi] = ok     ? lsum / fmaxf(fnp, 1.f)     : 0.f;
            }
        }
    }
    __syncthreads();
    if (threadIdx.x == 0) {
        float c = 0.f, r = 0.f, l = 0.f;
#pragma unroll
        for (int k = 0; k < NB; k++) { c += f_c[k]; r += f_r[k]; l += f_l[k]; }
        out[0] = c / (float)NB;
        out[1] = r / (float)NB;
        out[2] = l / (float)NB;
        g_ticket = 0;
#pragma unroll
        for (int k = 0; k < NB; k++) { g_poscnt[k] = 0; g_used[k] = 0u; }
    }
}

// ---------------------------------------------------------------------------
extern "C" void kernel_launch(void* const* d_in, const int* in_sizes, int n_in,
                              void* d_out, int out_size) {
    const float* cls = (const float*)d_in[0];
    const float* reg = (const float*)d_in[1];
    const float* loc = (const float*)d_in[2];
    const float* anc = (const float*)d_in[3];
    const float* ann = (const float*)d_in[4];
    float* out = (float*)d_out;

    pass1_kernel<<<dim3(BLOCKS_X, NB), TPB>>>(cls, reg, loc, anc, ann);
    pass2_kernel<<<dim3(P2X, NB), TPB>>>(ann, out);
}